// round 15
// baseline (speedup 1.0000x reference)
#include <cuda_runtime.h>
#include <cuda_fp16.h>
#include <cstdint>
#include <math.h>

#define B_  16
#define N_  4096
#define C_  512
#define H_  8
#define D_  64
#define CK_ 1024
#define SPLITS 16

// -------- scratch --------
__device__ __half g_qkh[(size_t)B_ * N_ * CK_];      // fp16 ROPED: q_rope | k_rope
__device__ float g_cos2[64 * 128];                   // [pos][kk]
__device__ float g_sin2[64 * 128];
__device__ float g_ksum[B_ * C_];                    // pre-rope k column sums (atomic)
__device__ float g_kv[B_ * H_ * D_ * D_];            // atomically accumulated, pre-scaled
__device__ __half g_Af16[(size_t)B_ * N_ * C_];      // x in fp16
__device__ __half g_Wf16[CK_ * C_];                  // W^T fp16, K-major

// ============ PTX helpers ============
__device__ __forceinline__ uint32_t smem_u32(const void* p) {
    uint32_t a;
    asm("{ .reg .u64 t; cvta.to.shared.u64 t, %1; cvt.u32.u64 %0, t; }" : "=r"(a) : "l"(p));
    return a;
}
__device__ __forceinline__ void cp16(uint32_t dst, const void* src) {
    asm volatile("cp.async.cg.shared.global [%0], [%1], 16;" :: "r"(dst), "l"(src) : "memory");
}
__device__ __forceinline__ void cp16z(uint32_t dst, const void* src, uint32_t srcsize) {
    asm volatile("cp.async.cg.shared.global [%0], [%1], 16, %2;"
                 :: "r"(dst), "l"(src), "r"(srcsize) : "memory");
}
#define CP_COMMIT() asm volatile("cp.async.commit_group;" ::: "memory")
#define CP_WAIT(n)  asm volatile("cp.async.wait_group %0;" :: "n"(n) : "memory")

__device__ __forceinline__ void ldsm_x4(uint32_t (&r)[4], uint32_t addr) {
    asm volatile("ldmatrix.sync.aligned.m8n8.x4.shared.b16 {%0,%1,%2,%3}, [%4];"
                 : "=r"(r[0]), "=r"(r[1]), "=r"(r[2]), "=r"(r[3]) : "r"(addr));
}
__device__ __forceinline__ void ldsm_x4_t(uint32_t (&r)[4], uint32_t addr) {
    asm volatile("ldmatrix.sync.aligned.m8n8.x4.trans.shared.b16 {%0,%1,%2,%3}, [%4];"
                 : "=r"(r[0]), "=r"(r[1]), "=r"(r[2]), "=r"(r[3]) : "r"(addr));
}
__device__ __forceinline__ uint32_t taddr(uint32_t base, int lane, int kbase, int mbase,
                                          int rowbytes) {
    const int k = kbase + (lane & 7) + ((lane >> 4) & 1) * 8;
    const int m = mbase + ((lane >> 3) & 1) * 8;
    return base + k * rowbytes + m * 2;
}
__device__ __forceinline__ void mma16816(float (&c)[4], const uint32_t (&a)[4],
                                         uint32_t b0, uint32_t b1) {
    asm volatile(
        "mma.sync.aligned.m16n8k16.row.col.f32.f16.f16.f32 "
        "{%0,%1,%2,%3}, {%4,%5,%6,%7}, {%8,%9}, {%0,%1,%2,%3};"
        : "+f"(c[0]), "+f"(c[1]), "+f"(c[2]), "+f"(c[3])
        : "r"(a[0]), "r"(a[1]), "r"(a[2]), "r"(a[3]), "r"(b0), "r"(b1));
}

// ============================================================
// K0: merged: convert x, convert W, rope table, zero ksum + kv
// ============================================================
__global__ void prep_kernel(const float* __restrict__ X, const float* __restrict__ W) {
    const int t = blockIdx.x * 256 + threadIdx.x;
    size_t i = (size_t)t * 4;
    float4 v = *(const float4*)(X + i);
    __half hv[4];
    hv[0] = __float2half_rn(v.x);
    hv[1] = __float2half_rn(v.y);
    hv[2] = __float2half_rn(v.z);
    hv[3] = __float2half_rn(v.w);
    *(uint2*)(g_Af16 + i) = *(uint2*)hv;

    if (t < C_ * CK_) {
        const int k = t >> 10, n = t & 1023;
        g_Wf16[n * 512 + k] = __float2half_rn(W[t]);
    }
    if (t < B_ * H_ * D_ * D_) g_kv[t] = 0.f;
    if (t < 8192) {
        const int pos = t >> 7, kk = t & 127;
        const float theta = powf(10000.0f, -(float)kk / 128.0f);
        const float a = (float)pos * theta;
        g_cos2[t] = cosf(a);
        g_sin2[t] = sinf(a);
        g_ksum[t] = 0.f;
    }
}

// ============================================================
// K1: fp16 mma GEMM, BK=64, 2-stage: fused bias+elu+1+ROPE (+kmean)
// ============================================================
#define BK      64
#define ROWB    144
#define BUF_SZ  (128 * ROWB)
#define STG_SZ  (2 * BUF_SZ)
#define GSMEM   (2 * STG_SZ)

__global__ __launch_bounds__(256, 2)
void qk_gemm_mma(const float* __restrict__ bias) {
    extern __shared__ char smem[];
    const uint32_t sb = smem_u32(smem);

    const int tid  = threadIdx.x;
    const int warp = tid >> 5, lane = tid & 31;
    const int wm = warp & 3;
    const int wn = warp >> 2;
    const int jt = blockIdx.x;
    const int n0 = jt * 128;
    const int m0 = blockIdx.y * 128;
    const bool isK = (jt >= 4);

    float acc[2][8][4];
#pragma unroll
    for (int a = 0; a < 2; a++)
#pragma unroll
        for (int b = 0; b < 8; b++)
#pragma unroll
            for (int c = 0; c < 4; c++) acc[a][b][c] = 0.f;

    auto prefetch = [&](int s, int k0) {
        const uint32_t st = sb + s * STG_SZ;
#pragma unroll
        for (int it = 0; it < 4; it++) {
            const int u   = tid + it * 256;
            const int row = u >> 3, c = u & 7;
            const uint32_t so = row * ROWB + c * 16;
            cp16(st + so,          g_Af16 + (size_t)(m0 + row) * 512 + k0 + c * 8);
            cp16(st + BUF_SZ + so, g_Wf16 + (size_t)(n0 + row) * 512 + k0 + c * 8);
        }
    };

    prefetch(0, 0); CP_COMMIT();

    const uint32_t aoff = (wm * 32 + (lane & 15)) * ROWB + (lane >> 4) * 16;
    const uint32_t boff = (wn * 64 + (lane & 15)) * ROWB + (lane >> 4) * 16;

#pragma unroll 1
    for (int ks = 0; ks < 8; ks++) {
        CP_WAIT(0);
        __syncthreads();
        if (ks < 7) { prefetch((ks + 1) & 1, (ks + 1) * BK); CP_COMMIT(); }

        const uint32_t st = sb + (ks & 1) * STG_SZ;
#pragma unroll
        for (int kk = 0; kk < 4; kk++) {
            const uint32_t kb = kk * 32;
            uint32_t ah[2][4], bh[4][4];
#pragma unroll
            for (int mt = 0; mt < 2; mt++)
                ldsm_x4(ah[mt], st + aoff + mt * (16 * ROWB) + kb);
#pragma unroll
            for (int nt = 0; nt < 4; nt++)
                ldsm_x4(bh[nt], st + BUF_SZ + boff + nt * (16 * ROWB) + kb);
#pragma unroll
            for (int mt = 0; mt < 2; mt++) {
#pragma unroll
                for (int nt = 0; nt < 4; nt++) {
                    mma16816(acc[mt][2 * nt + 0], ah[mt], bh[nt][0], bh[nt][2]);
                    mma16816(acc[mt][2 * nt + 1], ah[mt], bh[nt][1], bh[nt][3]);
                }
            }
        }
    }

    // epilogue: bias -> elu+1 -> (kmean reduce) -> rope -> fp16 store
    float* colsum = (float*)smem;
    if (isK) {
        __syncthreads();
        if (tid < 128) colsum[tid] = 0.f;
        __syncthreads();
    }

    float bja[8], bjb[8];
#pragma unroll
    for (int nt = 0; nt < 8; nt++) {
        const int col = n0 + wn * 64 + nt * 8 + (lane & 3) * 2;
        bja[nt] = __ldg(&bias[col]);
        bjb[nt] = __ldg(&bias[col + 1]);
    }

    float csum[8][2];
#pragma unroll
    for (int nt = 0; nt < 8; nt++) { csum[nt][0] = 0.f; csum[nt][1] = 0.f; }

#pragma unroll
    for (int mt = 0; mt < 2; mt++) {
        const int row0 = m0 + wm * 32 + mt * 16 + (lane >> 2);
#pragma unroll
        for (int nt = 0; nt < 8; nt++) {
            const int col = n0 + wn * 64 + nt * 8 + (lane & 3) * 2;
            float v0 = acc[mt][nt][0] + bja[nt];
            float v1 = acc[mt][nt][1] + bjb[nt];
            float v2 = acc[mt][nt][2] + bja[nt];
            float v3 = acc[mt][nt][3] + bjb[nt];
            v0 = (v0 > 0.f) ? (v0 + 1.f) : __expf(v0);
            v1 = (v1 > 0.f) ? (v1 + 1.f) : __expf(v1);
            v2 = (v2 > 0.f) ? (v2 + 1.f) : __expf(v2);
            v3 = (v3 > 0.f) ? (v3 + 1.f) : __expf(v3);

            if (isK) {
                csum[nt][0] += v0 + v2;
                csum[nt][1] += v1 + v3;
            }

            const int cfull = col & 511;
            const int kpair = cfull >> 1;
            const int kk = kpair & 127;
            const bool useH = (kpair < 128);

            const int nl0 = row0 & 4095;
            const int pos0 = useH ? (nl0 >> 6) : (nl0 & 63);
            const float c0 = g_cos2[pos0 * 128 + kk], s0 = g_sin2[pos0 * 128 + kk];
            const float r00 = v0 * c0 - v1 * s0;
            const float r01 = v0 * s0 + v1 * c0;

            const int nl1 = (row0 + 8) & 4095;
            const int pos1 = useH ? (nl1 >> 6) : (nl1 & 63);
            const float c1 = g_cos2[pos1 * 128 + kk], s1 = g_sin2[pos1 * 128 + kk];
            const float r10 = v2 * c1 - v3 * s1;
            const float r11 = v2 * s1 + v3 * c1;

            *(__half2*)&g_qkh[(size_t)row0 * 1024 + col]       = __floats2half2_rn(r00, r01);
            *(__half2*)&g_qkh[(size_t)(row0 + 8) * 1024 + col] = __floats2half2_rn(r10, r11);
        }
    }

    if (isK) {
#pragma unroll
        for (int nt = 0; nt < 8; nt++) {
#pragma unroll
            for (int o = 4; o <= 16; o <<= 1) {
                csum[nt][0] += __shfl_xor_sync(0xffffffffu, csum[nt][0], o);
                csum[nt][1] += __shfl_xor_sync(0xffffffffu, csum[nt][1], o);
            }
        }
        if (lane < 4) {
#pragma unroll
            for (int nt = 0; nt < 8; nt++) {
                const int lc = wn * 64 + nt * 8 + lane * 2;
                atomicAdd(&colsum[lc],     csum[nt][0]);
                atomicAdd(&colsum[lc + 1], csum[nt][1]);
            }
        }
        __syncthreads();
        if (tid < 128) {
            const int b = m0 >> 12;
            const int col512 = (n0 - 512) + tid;
            atomicAdd(&g_ksum[b * 512 + col512], colsum[tid]);
        }
    }
}

// ============================================================
// K3: kv partial — one-shot cp.async; global REDG accumulate (1/N folded)
// ============================================================
#define TROW 72
#define TROWB (TROW * 2)
#define KV_SMEM (2 * 256 * TROW * 2)

__global__ __launch_bounds__(128)
void kv_partial_tc() {
    extern __shared__ __half kvsm[];
    __half* kt = kvsm;
    __half* vt = kvsm + 256 * TROW;

    const int split = blockIdx.x, h = blockIdx.y, b = blockIdx.z;
    const int tid = threadIdx.x;
    const int warp = tid >> 5, lane = tid & 31;
    const int n0 = split * (N_ / SPLITS);
    const uint32_t ktb = smem_u32(kt);
    const uint32_t vtb = smem_u32(vt);

#pragma unroll
    for (int l = 0; l < 16; l++) {
        const int p   = tid + l * 128;
        const int row = p >> 3;
        const int c8  = (p & 7) * 8;
        const int n   = n0 + row;
        const uint32_t so = row * TROWB + c8 * 2;
        cp16(ktb + so, &g_qkh[((size_t)(b * N_ + n)) * CK_ + C_ + h * D_ + c8]);
        cp16(vtb + so, &g_Af16[((size_t)(b * N_ + n)) * C_ + h * D_ + c8]);
    }
    CP_COMMIT();

    float acc[8][4];
#pragma unroll
    for (int i = 0; i < 8; i++)
#pragma unroll
        for (int j = 0; j < 4; j++) acc[i][j] = 0.f;

    CP_WAIT(0);
    __syncthreads();

#pragma unroll
    for (int ks = 0; ks < 16; ks++) {
        uint32_t af[4];
        ldsm_x4_t(af, taddr(ktb, lane, ks * 16, warp * 16, TROWB));
#pragma unroll
        for (int nt = 0; nt < 4; nt++) {
            uint32_t bf[4];
            ldsm_x4_t(bf, taddr(vtb, lane, ks * 16, nt * 16, TROWB));
            mma16816(acc[nt * 2 + 0], af, bf[0], bf[2]);
            mma16816(acc[nt * 2 + 1], af, bf[1], bf[3]);
        }
    }

    const float sc = 1.0f / (float)N_;
    float* dst = &g_kv[((size_t)(b * H_ + h)) * (D_ * D_)];
    const int drow = warp * 16 + (lane >> 2);
#pragma unroll
    for (int eb = 0; eb < 8; eb++) {
        const int e = eb * 8 + (lane & 3) * 2;
        atomicAdd(&dst[drow * 64 + e],           acc[eb][0] * sc);
        atomicAdd(&dst[drow * 64 + e + 1],       acc[eb][1] * sc);
        atomicAdd(&dst[(drow + 8) * 64 + e],     acc[eb][2] * sc);
        atomicAdd(&dst[(drow + 8) * 64 + e + 1], acc[eb][3] * sc);
    }
}

// ============================================================
// K5: finalize: out = (q_rope @ kv) * z + lepe  (km scaled here)
// ============================================================
#define XROW 72
#define FIN_SMEM (64*4 + 576*4 + 256*4 + 64*TROW*2 + 256*TROW*2 + 6*64*XROW*2)

__global__ __launch_bounds__(256)
void finalize_tc(const float* __restrict__ LW, const float* __restrict__ LB,
                 float* __restrict__ out) {
    extern __shared__ float fsm[];
    float* km  = fsm;
    float* w9s = km + 64;
    float* zs  = w9s + 576;
    __half* kvt = (__half*)(zs + 256);
    __half* qs  = kvt + 64 * TROW;
    __half* xth = qs + 256 * TROW;
    const uint32_t kvtb = smem_u32(kvt);
    const uint32_t qsb  = smem_u32(qs);
    const uint32_t xthb = smem_u32(xth);

    const int hp4 = blockIdx.x;
    const int h   = blockIdx.y;
    const int b   = blockIdx.z;
    const int tid = threadIdx.x;
    const int warp = tid >> 5, lane = tid & 31;

    for (int i = tid; i < 2048; i += 256) {
        const int row = i >> 3, c8 = (i & 7) * 8;
        const int n = hp4 * 256 + row;
        cp16(qsb + row * TROWB + c8 * 2,
             &g_qkh[((size_t)(b * N_ + n)) * CK_ + h * D_ + c8]);
    }
    for (int i = tid; i < 3072; i += 256) {
        const int j   = i >> 9;
        const int rem = i & 511;
        const int w   = rem >> 3;
        const int e8  = (rem & 7) * 8;
        const int h2  = hp4 * 4 - 1 + j;
        const int h2c = (h2 < 0) ? 0 : ((h2 > 63) ? 63 : h2);
        const uint32_t valid = ((unsigned)h2 < 64u) ? 16u : 0u;
        cp16z(xthb + (j * (64 * XROW) + w * XROW + e8) * 2,
              &g_Af16[((size_t)(b * N_ + h2c * 64 + w)) * C_ + h * D_ + e8], valid);
    }
    CP_COMMIT();

    {
        const float* kvsrc = &g_kv[((size_t)(b * H_ + h)) * (D_ * D_)];
        for (int i = tid; i < 4096; i += 256) {
            const int d = i >> 6, e = i & 63;
            kvt[d * TROW + e] = __float2half_rn(kvsrc[i]);
        }
    }
    if (tid < 64) km[tid] = g_ksum[b * C_ + h * D_ + tid] * (1.0f / (float)N_);
    for (int i = tid; i < 576; i += 256) {
        const int p = i / 64, e = i % 64;
        w9s[i] = LW[p * C_ + h * D_ + e];
    }
    CP_WAIT(0);
    __syncthreads();

    // z per token — per-thread dot; useH uniform per head
    {
        const int token = tid;
        const bool useH = (h < 4);
        const int kkb = (h & 3) * 32;
        const int pos = useH ? (hp4 * 4 + (token >> 6)) : (token & 63);
        const float* crow = &g_cos2[pos * 128 + kkb];
        const float* srow = &g_sin2[pos * 128 + kkb];
        float zp = 0.f;
#pragma unroll
        for (int p = 0; p < 32; p++) {
            const float2 qv = __half22float2(*(const __half2*)&qs[token * TROW + 2 * p]);
            const float km0 = km[2 * p], km1 = km[2 * p + 1];
            const float cc = crow[p], ss = srow[p];
            zp += qv.x * (km0 * cc - km1 * ss) + qv.y * (km0 * ss + km1 * cc);
        }
        zs[token] = 1.0f / (zp + 1e-6f);
    }
    __syncwarp();

    // mma out = qs @ kvt
    float acc[2][8][4];
#pragma unroll
    for (int a = 0; a < 2; a++)
#pragma unroll
        for (int i = 0; i < 8; i++)
#pragma unroll
            for (int j = 0; j < 4; j++) acc[a][i][j] = 0.f;

    const int tb = warp * 32;
#pragma unroll
    for (int ks = 0; ks < 4; ks++) {
        uint32_t af[2][4];
#pragma unroll
        for (int mt = 0; mt < 2; mt++)
            ldsm_x4(af[mt], qsb + (tb + mt * 16 + (lane & 15)) * TROWB + ks * 32 + (lane >> 4) * 16);
#pragma unroll
        for (int nt = 0; nt < 4; nt++) {
            uint32_t bf[4];
            ldsm_x4_t(bf, taddr(kvtb, lane, ks * 16, nt * 16, TROWB));
#pragma unroll
            for (int mt = 0; mt < 2; mt++) {
                mma16816(acc[mt][nt * 2 + 0], af[mt], bf[0], bf[2]);
                mma16816(acc[mt][nt * 2 + 1], af[mt], bf[1], bf[3]);
            }
        }
    }

    // epilogue: z-scale + lepe + store
    const float* LBh = LB + h * D_;
#pragma unroll
    for (int mt = 0; mt < 2; mt++) {
#pragma unroll
        for (int half_ = 0; half_ < 2; half_++) {
            const int tok = tb + mt * 16 + (lane >> 2) + half_ * 8;
            const int rp  = tok >> 6;
            const int wc  = tok & 63;
            const float z = zs[tok];
            const size_t obase = ((size_t)(b * N_ + hp4 * 256 + tok)) * C_ + h * D_;
#pragma unroll
            for (int eb = 0; eb < 8; eb++) {
                const int e = eb * 8 + (lane & 3) * 2;
                float o0 = acc[mt][eb][half_ * 2 + 0] * z + LBh[e];
                float o1 = acc[mt][eb][half_ * 2 + 1] * z + LBh[e + 1];
#pragma unroll
                for (int di = 0; di < 3; di++) {
#pragma unroll
                    for (int dj = 0; dj < 3; dj++) {
                        const int w2 = wc + dj - 1;
                        if ((unsigned)w2 < 64u) {
                            const float wt0 = w9s[(di * 3 + dj) * 64 + e];
                            const float wt1 = w9s[(di * 3 + dj) * 64 + e + 1];
                            const float2 xv = __half22float2(
                                *(const __half2*)&xth[(rp + di) * (64 * XROW) + w2 * XROW + e]);
                            o0 += xv.x * wt0;
                            o1 += xv.y * wt1;
                        }
                    }
                }
                *(float2*)&out[obase + e] = make_float2(o0, o1);
            }
        }
    }
}

// ============================================================
extern "C" void kernel_launch(void* const* d_in, const int* in_sizes, int n_in,
                              void* d_out, int out_size) {
    (void)in_sizes; (void)n_in; (void)out_size;
    const float* x  = (const float*)d_in[0];
    const float* W  = (const float*)d_in[1];
    const float* qb = (const float*)d_in[2];
    const float* lw = (const float*)d_in[3];
    const float* lb = (const float*)d_in[4];
    float* out = (float*)d_out;

    cudaFuncSetAttribute(qk_gemm_mma, cudaFuncAttributeMaxDynamicSharedMemorySize, GSMEM);
    cudaFuncSetAttribute(kv_partial_tc, cudaFuncAttributeMaxDynamicSharedMemorySize, KV_SMEM);
    cudaFuncSetAttribute(finalize_tc, cudaFuncAttributeMaxDynamicSharedMemorySize, FIN_SMEM);

    prep_kernel<<<(int)(((size_t)B_ * N_ * C_ / 4) / 256), 256>>>(x, W);
    qk_gemm_mma<<<dim3(CK_ / 128, (B_ * N_) / 128), 256, GSMEM>>>(qb);
    kv_partial_tc<<<dim3(SPLITS, H_, B_), 128, KV_SMEM>>>();
    finalize_tc<<<dim3(16, H_, B_), 256, FIN_SMEM>>>(lw, lb, out);
}

// round 16
// speedup vs baseline: 1.0731x; 1.0731x over previous
#include <cuda_runtime.h>
#include <cuda_fp16.h>
#include <cstdint>
#include <math.h>

#define B_  16
#define N_  4096
#define C_  512
#define H_  8
#define D_  64
#define CK_ 1024
#define SPLITS 16

// -------- scratch --------
__device__ __half g_qkh[(size_t)B_ * N_ * CK_];      // fp16 ROPED: q_rope | k_rope
__device__ float g_cos2[64 * 128];                   // [pos][kk]
__device__ float g_sin2[64 * 128];
__device__ float g_ksum[B_ * C_];                    // pre-rope k column sums (atomic)
__device__ float g_kv[B_ * H_ * D_ * D_];            // atomically accumulated, pre-scaled
__device__ __half g_Af16[(size_t)B_ * N_ * C_];      // x in fp16
__device__ __half g_Wf16[CK_ * C_];                  // W^T fp16, K-major

// ============ PTX helpers ============
__device__ __forceinline__ uint32_t smem_u32(const void* p) {
    uint32_t a;
    asm("{ .reg .u64 t; cvta.to.shared.u64 t, %1; cvt.u32.u64 %0, t; }" : "=r"(a) : "l"(p));
    return a;
}
__device__ __forceinline__ void cp16(uint32_t dst, const void* src) {
    asm volatile("cp.async.cg.shared.global [%0], [%1], 16;" :: "r"(dst), "l"(src) : "memory");
}
__device__ __forceinline__ void cp16z(uint32_t dst, const void* src, uint32_t srcsize) {
    asm volatile("cp.async.cg.shared.global [%0], [%1], 16, %2;"
                 :: "r"(dst), "l"(src), "r"(srcsize) : "memory");
}
#define CP_COMMIT() asm volatile("cp.async.commit_group;" ::: "memory")
#define CP_WAIT(n)  asm volatile("cp.async.wait_group %0;" :: "n"(n) : "memory")

__device__ __forceinline__ void ldsm_x4(uint32_t (&r)[4], uint32_t addr) {
    asm volatile("ldmatrix.sync.aligned.m8n8.x4.shared.b16 {%0,%1,%2,%3}, [%4];"
                 : "=r"(r[0]), "=r"(r[1]), "=r"(r[2]), "=r"(r[3]) : "r"(addr));
}
__device__ __forceinline__ void ldsm_x4_t(uint32_t (&r)[4], uint32_t addr) {
    asm volatile("ldmatrix.sync.aligned.m8n8.x4.trans.shared.b16 {%0,%1,%2,%3}, [%4];"
                 : "=r"(r[0]), "=r"(r[1]), "=r"(r[2]), "=r"(r[3]) : "r"(addr));
}
__device__ __forceinline__ uint32_t taddr(uint32_t base, int lane, int kbase, int mbase,
                                          int rowbytes) {
    const int k = kbase + (lane & 7) + ((lane >> 4) & 1) * 8;
    const int m = mbase + ((lane >> 3) & 1) * 8;
    return base + k * rowbytes + m * 2;
}
__device__ __forceinline__ void mma16816(float (&c)[4], const uint32_t (&a)[4],
                                         uint32_t b0, uint32_t b1) {
    asm volatile(
        "mma.sync.aligned.m16n8k16.row.col.f32.f16.f16.f32 "
        "{%0,%1,%2,%3}, {%4,%5,%6,%7}, {%8,%9}, {%0,%1,%2,%3};"
        : "+f"(c[0]), "+f"(c[1]), "+f"(c[2]), "+f"(c[3])
        : "r"(a[0]), "r"(a[1]), "r"(a[2]), "r"(a[3]), "r"(b0), "r"(b1));
}

// ============================================================
// K0: merged: convert x, convert W, rope table, zero ksum + kv
// ============================================================
__global__ void prep_kernel(const float* __restrict__ X, const float* __restrict__ W) {
    const int t = blockIdx.x * 256 + threadIdx.x;
    size_t i = (size_t)t * 4;
    float4 v = *(const float4*)(X + i);
    __half hv[4];
    hv[0] = __float2half_rn(v.x);
    hv[1] = __float2half_rn(v.y);
    hv[2] = __float2half_rn(v.z);
    hv[3] = __float2half_rn(v.w);
    *(uint2*)(g_Af16 + i) = *(uint2*)hv;

    if (t < C_ * CK_) {
        const int k = t >> 10, n = t & 1023;
        g_Wf16[n * 512 + k] = __float2half_rn(W[t]);
    }
    if (t < B_ * H_ * D_ * D_) g_kv[t] = 0.f;
    if (t < 8192) {
        const int pos = t >> 7, kk = t & 127;
        const float theta = powf(10000.0f, -(float)kk / 128.0f);
        const float a = (float)pos * theta;
        g_cos2[t] = cosf(a);
        g_sin2[t] = sinf(a);
        g_ksum[t] = 0.f;
    }
}

// ============================================================
// K1: fp16 mma GEMM, BK=64, 2-stage: fused bias+elu+1+ROPE (+kmean)
// ============================================================
#define BK      64
#define ROWB    144
#define BUF_SZ  (128 * ROWB)
#define STG_SZ  (2 * BUF_SZ)
#define GSMEM   (2 * STG_SZ)

__global__ __launch_bounds__(256, 2)
void qk_gemm_mma(const float* __restrict__ bias) {
    extern __shared__ char smem[];
    const uint32_t sb = smem_u32(smem);

    const int tid  = threadIdx.x;
    const int warp = tid >> 5, lane = tid & 31;
    const int wm = warp & 3;
    const int wn = warp >> 2;
    const int jt = blockIdx.x;
    const int n0 = jt * 128;
    const int m0 = blockIdx.y * 128;
    const bool isK = (jt >= 4);

    float acc[2][8][4];
#pragma unroll
    for (int a = 0; a < 2; a++)
#pragma unroll
        for (int b = 0; b < 8; b++)
#pragma unroll
            for (int c = 0; c < 4; c++) acc[a][b][c] = 0.f;

    auto prefetch = [&](int s, int k0) {
        const uint32_t st = sb + s * STG_SZ;
#pragma unroll
        for (int it = 0; it < 4; it++) {
            const int u   = tid + it * 256;
            const int row = u >> 3, c = u & 7;
            const uint32_t so = row * ROWB + c * 16;
            cp16(st + so,          g_Af16 + (size_t)(m0 + row) * 512 + k0 + c * 8);
            cp16(st + BUF_SZ + so, g_Wf16 + (size_t)(n0 + row) * 512 + k0 + c * 8);
        }
    };

    prefetch(0, 0); CP_COMMIT();

    const uint32_t aoff = (wm * 32 + (lane & 15)) * ROWB + (lane >> 4) * 16;
    const uint32_t boff = (wn * 64 + (lane & 15)) * ROWB + (lane >> 4) * 16;

#pragma unroll 1
    for (int ks = 0; ks < 8; ks++) {
        CP_WAIT(0);
        __syncthreads();
        if (ks < 7) { prefetch((ks + 1) & 1, (ks + 1) * BK); CP_COMMIT(); }

        const uint32_t st = sb + (ks & 1) * STG_SZ;
#pragma unroll
        for (int kk = 0; kk < 4; kk++) {
            const uint32_t kb = kk * 32;
            uint32_t ah[2][4], bh[4][4];
#pragma unroll
            for (int mt = 0; mt < 2; mt++)
                ldsm_x4(ah[mt], st + aoff + mt * (16 * ROWB) + kb);
#pragma unroll
            for (int nt = 0; nt < 4; nt++)
                ldsm_x4(bh[nt], st + BUF_SZ + boff + nt * (16 * ROWB) + kb);
#pragma unroll
            for (int mt = 0; mt < 2; mt++) {
#pragma unroll
                for (int nt = 0; nt < 4; nt++) {
                    mma16816(acc[mt][2 * nt + 0], ah[mt], bh[nt][0], bh[nt][2]);
                    mma16816(acc[mt][2 * nt + 1], ah[mt], bh[nt][1], bh[nt][3]);
                }
            }
        }
    }

    // epilogue: bias -> elu+1 -> (kmean reduce) -> rope -> fp16 store
    float* colsum = (float*)smem;
    if (isK) {
        __syncthreads();
        if (tid < 128) colsum[tid] = 0.f;
        __syncthreads();
    }

    float bja[8], bjb[8];
#pragma unroll
    for (int nt = 0; nt < 8; nt++) {
        const int col = n0 + wn * 64 + nt * 8 + (lane & 3) * 2;
        bja[nt] = __ldg(&bias[col]);
        bjb[nt] = __ldg(&bias[col + 1]);
    }

    float csum[8][2];
#pragma unroll
    for (int nt = 0; nt < 8; nt++) { csum[nt][0] = 0.f; csum[nt][1] = 0.f; }

#pragma unroll
    for (int mt = 0; mt < 2; mt++) {
        const int row0 = m0 + wm * 32 + mt * 16 + (lane >> 2);
#pragma unroll
        for (int nt = 0; nt < 8; nt++) {
            const int col = n0 + wn * 64 + nt * 8 + (lane & 3) * 2;
            float v0 = acc[mt][nt][0] + bja[nt];
            float v1 = acc[mt][nt][1] + bjb[nt];
            float v2 = acc[mt][nt][2] + bja[nt];
            float v3 = acc[mt][nt][3] + bjb[nt];
            v0 = (v0 > 0.f) ? (v0 + 1.f) : __expf(v0);
            v1 = (v1 > 0.f) ? (v1 + 1.f) : __expf(v1);
            v2 = (v2 > 0.f) ? (v2 + 1.f) : __expf(v2);
            v3 = (v3 > 0.f) ? (v3 + 1.f) : __expf(v3);

            if (isK) {
                csum[nt][0] += v0 + v2;
                csum[nt][1] += v1 + v3;
            }

            const int cfull = col & 511;
            const int kpair = cfull >> 1;
            const int kk = kpair & 127;
            const bool useH = (kpair < 128);

            const int nl0 = row0 & 4095;
            const int pos0 = useH ? (nl0 >> 6) : (nl0 & 63);
            const float c0 = g_cos2[pos0 * 128 + kk], s0 = g_sin2[pos0 * 128 + kk];
            const float r00 = v0 * c0 - v1 * s0;
            const float r01 = v0 * s0 + v1 * c0;

            const int nl1 = (row0 + 8) & 4095;
            const int pos1 = useH ? (nl1 >> 6) : (nl1 & 63);
            const float c1 = g_cos2[pos1 * 128 + kk], s1 = g_sin2[pos1 * 128 + kk];
            const float r10 = v2 * c1 - v3 * s1;
            const float r11 = v2 * s1 + v3 * c1;

            *(__half2*)&g_qkh[(size_t)row0 * 1024 + col]       = __floats2half2_rn(r00, r01);
            *(__half2*)&g_qkh[(size_t)(row0 + 8) * 1024 + col] = __floats2half2_rn(r10, r11);
        }
    }

    if (isK) {
#pragma unroll
        for (int nt = 0; nt < 8; nt++) {
#pragma unroll
            for (int o = 4; o <= 16; o <<= 1) {
                csum[nt][0] += __shfl_xor_sync(0xffffffffu, csum[nt][0], o);
                csum[nt][1] += __shfl_xor_sync(0xffffffffu, csum[nt][1], o);
            }
        }
        if (lane < 4) {
#pragma unroll
            for (int nt = 0; nt < 8; nt++) {
                const int lc = wn * 64 + nt * 8 + lane * 2;
                atomicAdd(&colsum[lc],     csum[nt][0]);
                atomicAdd(&colsum[lc + 1], csum[nt][1]);
            }
        }
        __syncthreads();
        if (tid < 128) {
            const int b = m0 >> 12;
            const int col512 = (n0 - 512) + tid;
            atomicAdd(&g_ksum[b * 512 + col512], colsum[tid]);
        }
    }
}

// ============================================================
// K3: kv partial — one-shot cp.async; global REDG accumulate (1/N folded)
// ============================================================
#define TROW 72
#define TROWB (TROW * 2)
#define KV_SMEM (2 * 256 * TROW * 2)

__global__ __launch_bounds__(128)
void kv_partial_tc() {
    extern __shared__ __half kvsm[];
    __half* kt = kvsm;
    __half* vt = kvsm + 256 * TROW;

    const int split = blockIdx.x, h = blockIdx.y, b = blockIdx.z;
    const int tid = threadIdx.x;
    const int warp = tid >> 5, lane = tid & 31;
    const int n0 = split * (N_ / SPLITS);
    const uint32_t ktb = smem_u32(kt);
    const uint32_t vtb = smem_u32(vt);

#pragma unroll
    for (int l = 0; l < 16; l++) {
        const int p   = tid + l * 128;
        const int row = p >> 3;
        const int c8  = (p & 7) * 8;
        const int n   = n0 + row;
        const uint32_t so = row * TROWB + c8 * 2;
        cp16(ktb + so, &g_qkh[((size_t)(b * N_ + n)) * CK_ + C_ + h * D_ + c8]);
        cp16(vtb + so, &g_Af16[((size_t)(b * N_ + n)) * C_ + h * D_ + c8]);
    }
    CP_COMMIT();

    float acc[8][4];
#pragma unroll
    for (int i = 0; i < 8; i++)
#pragma unroll
        for (int j = 0; j < 4; j++) acc[i][j] = 0.f;

    CP_WAIT(0);
    __syncthreads();

#pragma unroll
    for (int ks = 0; ks < 16; ks++) {
        uint32_t af[4];
        ldsm_x4_t(af, taddr(ktb, lane, ks * 16, warp * 16, TROWB));
#pragma unroll
        for (int nt = 0; nt < 4; nt++) {
            uint32_t bf[4];
            ldsm_x4_t(bf, taddr(vtb, lane, ks * 16, nt * 16, TROWB));
            mma16816(acc[nt * 2 + 0], af, bf[0], bf[2]);
            mma16816(acc[nt * 2 + 1], af, bf[1], bf[3]);
        }
    }

    const float sc = 1.0f / (float)N_;
    float* dst = &g_kv[((size_t)(b * H_ + h)) * (D_ * D_)];
    const int drow = warp * 16 + (lane >> 2);
#pragma unroll
    for (int eb = 0; eb < 8; eb++) {
        const int e = eb * 8 + (lane & 3) * 2;
        atomicAdd(&dst[drow * 64 + e],           acc[eb][0] * sc);
        atomicAdd(&dst[drow * 64 + e + 1],       acc[eb][1] * sc);
        atomicAdd(&dst[(drow + 8) * 64 + e],     acc[eb][2] * sc);
        atomicAdd(&dst[(drow + 8) * 64 + e + 1], acc[eb][3] * sc);
    }
}

// ============================================================
// K5: finalize: out = (q_rope @ kv) * z + lepe
//     register-lean: attention result staged through smem (os = qs reuse)
// ============================================================
#define XROW 72
#define FIN_SMEM (64*4 + 576*4 + 256*4 + 64*TROW*2 + 256*TROW*2 + 6*64*XROW*2)

__global__ __launch_bounds__(256, 2)
void finalize_tc(const float* __restrict__ LW, const float* __restrict__ LB,
                 float* __restrict__ out) {
    extern __shared__ float fsm[];
    float* km  = fsm;
    float* w9s = km + 64;
    float* zs  = w9s + 576;
    __half* kvt = (__half*)(zs + 256);
    __half* qs  = kvt + 64 * TROW;           // [256][TROW]; becomes os after mma
    __half* xth = qs + 256 * TROW;           // [6][64][XROW]
    const uint32_t kvtb = smem_u32(kvt);
    const uint32_t qsb  = smem_u32(qs);
    const uint32_t xthb = smem_u32(xth);

    const int hp4 = blockIdx.x;
    const int h   = blockIdx.y;
    const int b   = blockIdx.z;
    const int tid = threadIdx.x;
    const int warp = tid >> 5, lane = tid & 31;

    // phase 1: async q tile + async halo + sync loads
    for (int i = tid; i < 2048; i += 256) {
        const int row = i >> 3, c8 = (i & 7) * 8;
        const int n = hp4 * 256 + row;
        cp16(qsb + row * TROWB + c8 * 2,
             &g_qkh[((size_t)(b * N_ + n)) * CK_ + h * D_ + c8]);
    }
    for (int i = tid; i < 3072; i += 256) {
        const int j   = i >> 9;
        const int rem = i & 511;
        const int w   = rem >> 3;
        const int e8  = (rem & 7) * 8;
        const int h2  = hp4 * 4 - 1 + j;
        const int h2c = (h2 < 0) ? 0 : ((h2 > 63) ? 63 : h2);
        const uint32_t valid = ((unsigned)h2 < 64u) ? 16u : 0u;
        cp16z(xthb + (j * (64 * XROW) + w * XROW + e8) * 2,
              &g_Af16[((size_t)(b * N_ + h2c * 64 + w)) * C_ + h * D_ + e8], valid);
    }
    CP_COMMIT();

    {
        const float* kvsrc = &g_kv[((size_t)(b * H_ + h)) * (D_ * D_)];
        for (int i = tid; i < 4096; i += 256) {
            const int d = i >> 6, e = i & 63;
            kvt[d * TROW + e] = __float2half_rn(kvsrc[i]);
        }
    }
    if (tid < 64) km[tid] = g_ksum[b * C_ + h * D_ + tid] * (1.0f / (float)N_);
    for (int i = tid; i < 576; i += 256) {
        const int p = i / 64, e = i % 64;
        w9s[i] = LW[p * C_ + h * D_ + e];
    }
    CP_WAIT(0);
    __syncthreads();

    // phase 2: z per token — per-thread dot; useH uniform per head
    {
        const int token = tid;
        const bool useH = (h < 4);
        const int kkb = (h & 3) * 32;
        const int pos = useH ? (hp4 * 4 + (token >> 6)) : (token & 63);
        const float* crow = &g_cos2[pos * 128 + kkb];
        const float* srow = &g_sin2[pos * 128 + kkb];
        float zp = 0.f;
#pragma unroll
        for (int p = 0; p < 32; p++) {
            const float2 qv = __half22float2(*(const __half2*)&qs[token * TROW + 2 * p]);
            const float km0 = km[2 * p], km1 = km[2 * p + 1];
            const float cc = crow[p], ss = srow[p];
            zp += qv.x * (km0 * cc - km1 * ss) + qv.y * (km0 * ss + km1 * cc);
        }
        zs[token] = 1.0f / (zp + 1e-6f);
    }
    __syncwarp();

    // phase 3: mma out = qs @ kvt, then stage acc*z back into qs (os)
    {
        float acc[2][8][4];
#pragma unroll
        for (int a = 0; a < 2; a++)
#pragma unroll
            for (int i = 0; i < 8; i++)
#pragma unroll
                for (int j = 0; j < 4; j++) acc[a][i][j] = 0.f;

        const int tb = warp * 32;
#pragma unroll
        for (int ks = 0; ks < 4; ks++) {
            uint32_t af[2][4];
#pragma unroll
            for (int mt = 0; mt < 2; mt++)
                ldsm_x4(af[mt], qsb + (tb + mt * 16 + (lane & 15)) * TROWB + ks * 32 + (lane >> 4) * 16);
#pragma unroll
            for (int nt = 0; nt < 4; nt++) {
                uint32_t bf[4];
                ldsm_x4_t(bf, taddr(kvtb, lane, ks * 16, nt * 16, TROWB));
#pragma unroll
                for (int mt = 0; mt < 2; mt++) {
                    mma16816(acc[mt][nt * 2 + 0], af[mt], bf[0], bf[2]);
                    mma16816(acc[mt][nt * 2 + 1], af[mt], bf[1], bf[3]);
                }
            }
        }

        // stage: os[token][e] = acc * z   (fp16; warp-local rows, no sync needed)
        __half* os = qs;
#pragma unroll
        for (int mt = 0; mt < 2; mt++) {
#pragma unroll
            for (int half_ = 0; half_ < 2; half_++) {
                const int tok = tb + mt * 16 + (lane >> 2) + half_ * 8;
                const float z = zs[tok];
#pragma unroll
                for (int eb = 0; eb < 8; eb++) {
                    const int e = eb * 8 + (lane & 3) * 2;
                    *(__half2*)&os[tok * TROW + e] = __floats2half2_rn(
                        acc[mt][eb][half_ * 2 + 0] * z,
                        acc[mt][eb][half_ * 2 + 1] * z);
                }
            }
        }
    }
    __syncthreads();

    // phase 4: register-lean lepe + store. thread = (e, tg); 64 tokens each
    {
        const __half* os = qs;
        const int e  = tid & 63;
        const int tg = tid >> 6;            // spatial row 0..3
        float w9[9];
#pragma unroll
        for (int p = 0; p < 9; p++) w9[p] = w9s[p * 64 + e];
        const float lb = LB[h * D_ + e];

#pragma unroll 1
        for (int wc = 0; wc < 64; wc++) {
            const int token = tg * 64 + wc;
            float o = __half2float(os[token * TROW + e]) + lb;
#pragma unroll
            for (int di = 0; di < 3; di++) {
#pragma unroll
                for (int dj = 0; dj < 3; dj++) {
                    const int w2 = wc + dj - 1;
                    if ((unsigned)w2 < 64u)
                        o += __half2float(xth[(tg + di) * (64 * XROW) + w2 * XROW + e]) * w9[di * 3 + dj];
                }
            }
            out[((size_t)(b * N_ + hp4 * 256 + token)) * C_ + h * D_ + e] = o;
        }
    }
}

// ============================================================
extern "C" void kernel_launch(void* const* d_in, const int* in_sizes, int n_in,
                              void* d_out, int out_size) {
    (void)in_sizes; (void)n_in; (void)out_size;
    const float* x  = (const float*)d_in[0];
    const float* W  = (const float*)d_in[1];
    const float* qb = (const float*)d_in[2];
    const float* lw = (const float*)d_in[3];
    const float* lb = (const float*)d_in[4];
    float* out = (float*)d_out;

    cudaFuncSetAttribute(qk_gemm_mma, cudaFuncAttributeMaxDynamicSharedMemorySize, GSMEM);
    cudaFuncSetAttribute(kv_partial_tc, cudaFuncAttributeMaxDynamicSharedMemorySize, KV_SMEM);
    cudaFuncSetAttribute(finalize_tc, cudaFuncAttributeMaxDynamicSharedMemorySize, FIN_SMEM);

    prep_kernel<<<(int)(((size_t)B_ * N_ * C_ / 4) / 256), 256>>>(x, W);
    qk_gemm_mma<<<dim3(CK_ / 128, (B_ * N_) / 128), 256, GSMEM>>>(qb);
    kv_partial_tc<<<dim3(SPLITS, H_, B_), 128, KV_SMEM>>>();
    finalize_tc<<<dim3(16, H_, B_), 256, FIN_SMEM>>>(lw, lb, out);
}

// round 17
// speedup vs baseline: 1.1072x; 1.0318x over previous
#include <cuda_runtime.h>
#include <cuda_fp16.h>
#include <cstdint>
#include <math.h>

#define B_  16
#define N_  4096
#define C_  512
#define H_  8
#define D_  64
#define CK_ 1024
#define SPLITS 16

// -------- scratch --------
__device__ __half g_qkh[(size_t)B_ * N_ * CK_];      // fp16 ROPED: q_rope | k_rope
__device__ float g_cos2[64 * 128];                   // [pos][kk]
__device__ float g_sin2[64 * 128];
__device__ float g_ksum[B_ * C_];                    // pre-rope k column sums (atomic)
__device__ float g_kv[B_ * H_ * D_ * D_];            // atomically accumulated, pre-scaled
__device__ __half g_Af16[(size_t)B_ * N_ * C_];      // x in fp16
__device__ __half g_Wf16[CK_ * C_];                  // W^T fp16, K-major

// ============ PTX helpers ============
__device__ __forceinline__ uint32_t smem_u32(const void* p) {
    uint32_t a;
    asm("{ .reg .u64 t; cvta.to.shared.u64 t, %1; cvt.u32.u64 %0, t; }" : "=r"(a) : "l"(p));
    return a;
}
__device__ __forceinline__ void cp16(uint32_t dst, const void* src) {
    asm volatile("cp.async.cg.shared.global [%0], [%1], 16;" :: "r"(dst), "l"(src) : "memory");
}
__device__ __forceinline__ void cp16z(uint32_t dst, const void* src, uint32_t srcsize) {
    asm volatile("cp.async.cg.shared.global [%0], [%1], 16, %2;"
                 :: "r"(dst), "l"(src), "r"(srcsize) : "memory");
}
#define CP_COMMIT() asm volatile("cp.async.commit_group;" ::: "memory")
#define CP_WAIT(n)  asm volatile("cp.async.wait_group %0;" :: "n"(n) : "memory")

__device__ __forceinline__ void ldsm_x4(uint32_t (&r)[4], uint32_t addr) {
    asm volatile("ldmatrix.sync.aligned.m8n8.x4.shared.b16 {%0,%1,%2,%3}, [%4];"
                 : "=r"(r[0]), "=r"(r[1]), "=r"(r[2]), "=r"(r[3]) : "r"(addr));
}
__device__ __forceinline__ void ldsm_x4_t(uint32_t (&r)[4], uint32_t addr) {
    asm volatile("ldmatrix.sync.aligned.m8n8.x4.trans.shared.b16 {%0,%1,%2,%3}, [%4];"
                 : "=r"(r[0]), "=r"(r[1]), "=r"(r[2]), "=r"(r[3]) : "r"(addr));
}
__device__ __forceinline__ uint32_t taddr(uint32_t base, int lane, int kbase, int mbase,
                                          int rowbytes) {
    const int k = kbase + (lane & 7) + ((lane >> 4) & 1) * 8;
    const int m = mbase + ((lane >> 3) & 1) * 8;
    return base + k * rowbytes + m * 2;
}
__device__ __forceinline__ void mma16816(float (&c)[4], const uint32_t (&a)[4],
                                         uint32_t b0, uint32_t b1) {
    asm volatile(
        "mma.sync.aligned.m16n8k16.row.col.f32.f16.f16.f32 "
        "{%0,%1,%2,%3}, {%4,%5,%6,%7}, {%8,%9}, {%0,%1,%2,%3};"
        : "+f"(c[0]), "+f"(c[1]), "+f"(c[2]), "+f"(c[3])
        : "r"(a[0]), "r"(a[1]), "r"(a[2]), "r"(a[3]), "r"(b0), "r"(b1));
}

// ============================================================
// K0: merged: convert x, convert W, rope table, zero ksum + kv
// ============================================================
__global__ void prep_kernel(const float* __restrict__ X, const float* __restrict__ W) {
    const int t = blockIdx.x * 256 + threadIdx.x;
    size_t i = (size_t)t * 4;
    float4 v = *(const float4*)(X + i);
    __half hv[4];
    hv[0] = __float2half_rn(v.x);
    hv[1] = __float2half_rn(v.y);
    hv[2] = __float2half_rn(v.z);
    hv[3] = __float2half_rn(v.w);
    *(uint2*)(g_Af16 + i) = *(uint2*)hv;

    if (t < C_ * CK_) {
        const int k = t >> 10, n = t & 1023;
        g_Wf16[n * 512 + k] = __float2half_rn(W[t]);
    }
    if (t < B_ * H_ * D_ * D_) g_kv[t] = 0.f;
    if (t < 8192) {
        const int pos = t >> 7, kk = t & 127;
        const float theta = powf(10000.0f, -(float)kk / 128.0f);
        const float a = (float)pos * theta;
        g_cos2[t] = cosf(a);
        g_sin2[t] = sinf(a);
        g_ksum[t] = 0.f;
    }
}

// ============================================================
// K1: fp16 mma GEMM, BK=64, 2-stage: fused bias+elu+1+ROPE (+kmean)
// ============================================================
#define BK      64
#define ROWB    144
#define BUF_SZ  (128 * ROWB)
#define STG_SZ  (2 * BUF_SZ)
#define GSMEM   (2 * STG_SZ)

__global__ __launch_bounds__(256, 2)
void qk_gemm_mma(const float* __restrict__ bias) {
    extern __shared__ char smem[];
    const uint32_t sb = smem_u32(smem);

    const int tid  = threadIdx.x;
    const int warp = tid >> 5, lane = tid & 31;
    const int wm = warp & 3;
    const int wn = warp >> 2;
    const int jt = blockIdx.x;
    const int n0 = jt * 128;
    const int m0 = blockIdx.y * 128;
    const bool isK = (jt >= 4);

    float acc[2][8][4];
#pragma unroll
    for (int a = 0; a < 2; a++)
#pragma unroll
        for (int b = 0; b < 8; b++)
#pragma unroll
            for (int c = 0; c < 4; c++) acc[a][b][c] = 0.f;

    auto prefetch = [&](int s, int k0) {
        const uint32_t st = sb + s * STG_SZ;
#pragma unroll
        for (int it = 0; it < 4; it++) {
            const int u   = tid + it * 256;
            const int row = u >> 3, c = u & 7;
            const uint32_t so = row * ROWB + c * 16;
            cp16(st + so,          g_Af16 + (size_t)(m0 + row) * 512 + k0 + c * 8);
            cp16(st + BUF_SZ + so, g_Wf16 + (size_t)(n0 + row) * 512 + k0 + c * 8);
        }
    };

    prefetch(0, 0); CP_COMMIT();

    const uint32_t aoff = (wm * 32 + (lane & 15)) * ROWB + (lane >> 4) * 16;
    const uint32_t boff = (wn * 64 + (lane & 15)) * ROWB + (lane >> 4) * 16;

#pragma unroll 1
    for (int ks = 0; ks < 8; ks++) {
        CP_WAIT(0);
        __syncthreads();
        if (ks < 7) { prefetch((ks + 1) & 1, (ks + 1) * BK); CP_COMMIT(); }

        const uint32_t st = sb + (ks & 1) * STG_SZ;
#pragma unroll
        for (int kk = 0; kk < 4; kk++) {
            const uint32_t kb = kk * 32;
            uint32_t ah[2][4], bh[4][4];
#pragma unroll
            for (int mt = 0; mt < 2; mt++)
                ldsm_x4(ah[mt], st + aoff + mt * (16 * ROWB) + kb);
#pragma unroll
            for (int nt = 0; nt < 4; nt++)
                ldsm_x4(bh[nt], st + BUF_SZ + boff + nt * (16 * ROWB) + kb);
#pragma unroll
            for (int mt = 0; mt < 2; mt++) {
#pragma unroll
                for (int nt = 0; nt < 4; nt++) {
                    mma16816(acc[mt][2 * nt + 0], ah[mt], bh[nt][0], bh[nt][2]);
                    mma16816(acc[mt][2 * nt + 1], ah[mt], bh[nt][1], bh[nt][3]);
                }
            }
        }
    }

    // epilogue
    float* colsum = (float*)smem;
    if (isK) {
        __syncthreads();
        if (tid < 128) colsum[tid] = 0.f;
        __syncthreads();
    }

    float bja[8], bjb[8];
#pragma unroll
    for (int nt = 0; nt < 8; nt++) {
        const int col = n0 + wn * 64 + nt * 8 + (lane & 3) * 2;
        bja[nt] = __ldg(&bias[col]);
        bjb[nt] = __ldg(&bias[col + 1]);
    }

    float csum[8][2];
#pragma unroll
    for (int nt = 0; nt < 8; nt++) { csum[nt][0] = 0.f; csum[nt][1] = 0.f; }

#pragma unroll
    for (int mt = 0; mt < 2; mt++) {
        const int row0 = m0 + wm * 32 + mt * 16 + (lane >> 2);
#pragma unroll
        for (int nt = 0; nt < 8; nt++) {
            const int col = n0 + wn * 64 + nt * 8 + (lane & 3) * 2;
            float v0 = acc[mt][nt][0] + bja[nt];
            float v1 = acc[mt][nt][1] + bjb[nt];
            float v2 = acc[mt][nt][2] + bja[nt];
            float v3 = acc[mt][nt][3] + bjb[nt];
            v0 = (v0 > 0.f) ? (v0 + 1.f) : __expf(v0);
            v1 = (v1 > 0.f) ? (v1 + 1.f) : __expf(v1);
            v2 = (v2 > 0.f) ? (v2 + 1.f) : __expf(v2);
            v3 = (v3 > 0.f) ? (v3 + 1.f) : __expf(v3);

            if (isK) {
                csum[nt][0] += v0 + v2;
                csum[nt][1] += v1 + v3;
            }

            const int cfull = col & 511;
            const int kpair = cfull >> 1;
            const int kk = kpair & 127;
            const bool useH = (kpair < 128);

            const int nl0 = row0 & 4095;
            const int pos0 = useH ? (nl0 >> 6) : (nl0 & 63);
            const float c0 = g_cos2[pos0 * 128 + kk], s0 = g_sin2[pos0 * 128 + kk];
            const float r00 = v0 * c0 - v1 * s0;
            const float r01 = v0 * s0 + v1 * c0;

            const int nl1 = (row0 + 8) & 4095;
            const int pos1 = useH ? (nl1 >> 6) : (nl1 & 63);
            const float c1 = g_cos2[pos1 * 128 + kk], s1 = g_sin2[pos1 * 128 + kk];
            const float r10 = v2 * c1 - v3 * s1;
            const float r11 = v2 * s1 + v3 * c1;

            *(__half2*)&g_qkh[(size_t)row0 * 1024 + col]       = __floats2half2_rn(r00, r01);
            *(__half2*)&g_qkh[(size_t)(row0 + 8) * 1024 + col] = __floats2half2_rn(r10, r11);
        }
    }

    if (isK) {
#pragma unroll
        for (int nt = 0; nt < 8; nt++) {
#pragma unroll
            for (int o = 4; o <= 16; o <<= 1) {
                csum[nt][0] += __shfl_xor_sync(0xffffffffu, csum[nt][0], o);
                csum[nt][1] += __shfl_xor_sync(0xffffffffu, csum[nt][1], o);
            }
        }
        if (lane < 4) {
#pragma unroll
            for (int nt = 0; nt < 8; nt++) {
                const int lc = wn * 64 + nt * 8 + lane * 2;
                atomicAdd(&colsum[lc],     csum[nt][0]);
                atomicAdd(&colsum[lc + 1], csum[nt][1]);
            }
        }
        __syncthreads();
        if (tid < 128) {
            const int b = m0 >> 12;
            const int col512 = (n0 - 512) + tid;
            atomicAdd(&g_ksum[b * 512 + col512], colsum[tid]);
        }
    }
}

// ============================================================
// K3: kv partial — one-shot cp.async; global REDG accumulate (1/N folded)
// ============================================================
#define TROW 72
#define TROWB (TROW * 2)
#define KV_SMEM (2 * 256 * TROW * 2)

__global__ __launch_bounds__(128)
void kv_partial_tc() {
    extern __shared__ __half kvsm[];
    __half* kt = kvsm;
    __half* vt = kvsm + 256 * TROW;

    const int split = blockIdx.x, h = blockIdx.y, b = blockIdx.z;
    const int tid = threadIdx.x;
    const int warp = tid >> 5, lane = tid & 31;
    const int n0 = split * (N_ / SPLITS);
    const uint32_t ktb = smem_u32(kt);
    const uint32_t vtb = smem_u32(vt);

#pragma unroll
    for (int l = 0; l < 16; l++) {
        const int p   = tid + l * 128;
        const int row = p >> 3;
        const int c8  = (p & 7) * 8;
        const int n   = n0 + row;
        const uint32_t so = row * TROWB + c8 * 2;
        cp16(ktb + so, &g_qkh[((size_t)(b * N_ + n)) * CK_ + C_ + h * D_ + c8]);
        cp16(vtb + so, &g_Af16[((size_t)(b * N_ + n)) * C_ + h * D_ + c8]);
    }
    CP_COMMIT();

    float acc[8][4];
#pragma unroll
    for (int i = 0; i < 8; i++)
#pragma unroll
        for (int j = 0; j < 4; j++) acc[i][j] = 0.f;

    CP_WAIT(0);
    __syncthreads();

#pragma unroll
    for (int ks = 0; ks < 16; ks++) {
        uint32_t af[4];
        ldsm_x4_t(af, taddr(ktb, lane, ks * 16, warp * 16, TROWB));
#pragma unroll
        for (int nt = 0; nt < 4; nt++) {
            uint32_t bf[4];
            ldsm_x4_t(bf, taddr(vtb, lane, ks * 16, nt * 16, TROWB));
            mma16816(acc[nt * 2 + 0], af, bf[0], bf[2]);
            mma16816(acc[nt * 2 + 1], af, bf[1], bf[3]);
        }
    }

    const float sc = 1.0f / (float)N_;
    float* dst = &g_kv[((size_t)(b * H_ + h)) * (D_ * D_)];
    const int drow = warp * 16 + (lane >> 2);
#pragma unroll
    for (int eb = 0; eb < 8; eb++) {
        const int e = eb * 8 + (lane & 3) * 2;
        atomicAdd(&dst[drow * 64 + e],           acc[eb][0] * sc);
        atomicAdd(&dst[drow * 64 + e + 1],       acc[eb][1] * sc);
        atomicAdd(&dst[(drow + 8) * 64 + e],     acc[eb][2] * sc);
        atomicAdd(&dst[(drow + 8) * 64 + e + 1], acc[eb][3] * sc);
    }
}

// ============================================================
// K5: finalize: out = (q_rope @ kv) * z + lepe
//     phase-4: half2 channels + 3x3 register sliding window
// ============================================================
#define XROW 72
#define FIN_SMEM (64*4 + 576*4 + 256*4 + 64*TROW*2 + 256*TROW*2 + 6*64*XROW*2)

__global__ __launch_bounds__(256, 2)
void finalize_tc(const float* __restrict__ LW, const float* __restrict__ LB,
                 float* __restrict__ out) {
    extern __shared__ float fsm[];
    float* km  = fsm;
    float* w9s = km + 64;
    float* zs  = w9s + 576;
    __half* kvt = (__half*)(zs + 256);
    __half* qs  = kvt + 64 * TROW;           // [256][TROW]; becomes os after mma
    __half* xth = qs + 256 * TROW;           // [6][64][XROW]
    const uint32_t kvtb = smem_u32(kvt);
    const uint32_t qsb  = smem_u32(qs);
    const uint32_t xthb = smem_u32(xth);

    const int hp4 = blockIdx.x;
    const int h   = blockIdx.y;
    const int b   = blockIdx.z;
    const int tid = threadIdx.x;
    const int warp = tid >> 5, lane = tid & 31;

    // phase 1: async q tile + async halo + sync loads
    for (int i = tid; i < 2048; i += 256) {
        const int row = i >> 3, c8 = (i & 7) * 8;
        const int n = hp4 * 256 + row;
        cp16(qsb + row * TROWB + c8 * 2,
             &g_qkh[((size_t)(b * N_ + n)) * CK_ + h * D_ + c8]);
    }
    for (int i = tid; i < 3072; i += 256) {
        const int j   = i >> 9;
        const int rem = i & 511;
        const int w   = rem >> 3;
        const int e8  = (rem & 7) * 8;
        const int h2  = hp4 * 4 - 1 + j;
        const int h2c = (h2 < 0) ? 0 : ((h2 > 63) ? 63 : h2);
        const uint32_t valid = ((unsigned)h2 < 64u) ? 16u : 0u;
        cp16z(xthb + (j * (64 * XROW) + w * XROW + e8) * 2,
              &g_Af16[((size_t)(b * N_ + h2c * 64 + w)) * C_ + h * D_ + e8], valid);
    }
    CP_COMMIT();

    {
        const float* kvsrc = &g_kv[((size_t)(b * H_ + h)) * (D_ * D_)];
        for (int i = tid; i < 4096; i += 256) {
            const int d = i >> 6, e = i & 63;
            kvt[d * TROW + e] = __float2half_rn(kvsrc[i]);
        }
    }
    if (tid < 64) km[tid] = g_ksum[b * C_ + h * D_ + tid] * (1.0f / (float)N_);
    for (int i = tid; i < 576; i += 256) {
        const int p = i / 64, e = i % 64;
        w9s[i] = LW[p * C_ + h * D_ + e];
    }
    CP_WAIT(0);
    __syncthreads();

    // phase 2: z per token
    {
        const int token = tid;
        const bool useH = (h < 4);
        const int kkb = (h & 3) * 32;
        const int pos = useH ? (hp4 * 4 + (token >> 6)) : (token & 63);
        const float* crow = &g_cos2[pos * 128 + kkb];
        const float* srow = &g_sin2[pos * 128 + kkb];
        float zp = 0.f;
#pragma unroll
        for (int p = 0; p < 32; p++) {
            const float2 qv = __half22float2(*(const __half2*)&qs[token * TROW + 2 * p]);
            const float km0 = km[2 * p], km1 = km[2 * p + 1];
            const float cc = crow[p], ss = srow[p];
            zp += qv.x * (km0 * cc - km1 * ss) + qv.y * (km0 * ss + km1 * cc);
        }
        zs[token] = 1.0f / (zp + 1e-6f);
    }
    __syncwarp();

    // phase 3: mma out = qs @ kvt, stage acc*z into os (= qs)
    {
        float acc[2][8][4];
#pragma unroll
        for (int a = 0; a < 2; a++)
#pragma unroll
            for (int i = 0; i < 8; i++)
#pragma unroll
                for (int j = 0; j < 4; j++) acc[a][i][j] = 0.f;

        const int tb = warp * 32;
#pragma unroll
        for (int ks = 0; ks < 4; ks++) {
            uint32_t af[2][4];
#pragma unroll
            for (int mt = 0; mt < 2; mt++)
                ldsm_x4(af[mt], qsb + (tb + mt * 16 + (lane & 15)) * TROWB + ks * 32 + (lane >> 4) * 16);
#pragma unroll
            for (int nt = 0; nt < 4; nt++) {
                uint32_t bf[4];
                ldsm_x4_t(bf, taddr(kvtb, lane, ks * 16, nt * 16, TROWB));
#pragma unroll
                for (int mt = 0; mt < 2; mt++) {
                    mma16816(acc[mt][nt * 2 + 0], af[mt], bf[0], bf[2]);
                    mma16816(acc[mt][nt * 2 + 1], af[mt], bf[1], bf[3]);
                }
            }
        }

        __half* os = qs;
#pragma unroll
        for (int mt = 0; mt < 2; mt++) {
#pragma unroll
            for (int half_ = 0; half_ < 2; half_++) {
                const int tok = tb + mt * 16 + (lane >> 2) + half_ * 8;
                const float z = zs[tok];
#pragma unroll
                for (int eb = 0; eb < 8; eb++) {
                    const int e = eb * 8 + (lane & 3) * 2;
                    *(__half2*)&os[tok * TROW + e] = __floats2half2_rn(
                        acc[mt][eb][half_ * 2 + 0] * z,
                        acc[mt][eb][half_ * 2 + 1] * z);
                }
            }
        }
    }
    __syncthreads();

    // phase 4: half2 lepe with 3x3 sliding window.
    // thread = (ep channel-pair, tg token-group): row = tg>>1, wbase = (tg&1)*32
    {
        const __half* os = qs;
        const int ep = tid & 31;
        const int tg = tid >> 5;
        const int row = tg >> 1;
        const int wbase = (tg & 1) * 32;
        const int e = ep * 2;

        float w9a[9], w9b[9];
#pragma unroll
        for (int p = 0; p < 9; p++) {
            w9a[p] = w9s[p * 64 + e];
            w9b[p] = w9s[p * 64 + e + 1];
        }
        const float lb0 = LB[h * D_ + e];
        const float lb1 = LB[h * D_ + e + 1];

        // window xw[di][dj] covers w2 = wc-1+dj for current wc
        float2 xw[3][3];
#pragma unroll
        for (int di = 0; di < 3; di++) {
#pragma unroll
            for (int dj = 0; dj < 3; dj++) {
                const int w2 = wbase - 1 + dj;
                xw[di][dj] = ((unsigned)w2 < 64u)
                    ? __half22float2(*(const __half2*)&xth[(row + di) * (64 * XROW) + w2 * XROW + e])
                    : make_float2(0.f, 0.f);
            }
        }

#pragma unroll 1
        for (int wc = wbase; wc < wbase + 32; wc++) {
            const int token = row * 64 + wc;
            const float2 ov = __half22float2(*(const __half2*)&os[token * TROW + e]);
            float o0 = ov.x + lb0;
            float o1 = ov.y + lb1;
#pragma unroll
            for (int di = 0; di < 3; di++) {
                o0 += xw[di][0].x * w9a[di * 3] + xw[di][1].x * w9a[di * 3 + 1] + xw[di][2].x * w9a[di * 3 + 2];
                o1 += xw[di][0].y * w9b[di * 3] + xw[di][1].y * w9b[di * 3 + 1] + xw[di][2].y * w9b[di * 3 + 2];
            }
            *(float2*)&out[((size_t)(b * N_ + hp4 * 256 + token)) * C_ + h * D_ + e] =
                make_float2(o0, o1);

            // slide window
            const int w2 = wc + 2;
#pragma unroll
            for (int di = 0; di < 3; di++) {
                xw[di][0] = xw[di][1];
                xw[di][1] = xw[di][2];
                xw[di][2] = ((unsigned)w2 < 64u)
                    ? __half22float2(*(const __half2*)&xth[(row + di) * (64 * XROW) + w2 * XROW + e])
                    : make_float2(0.f, 0.f);
            }
        }
    }
}

// ============================================================
extern "C" void kernel_launch(void* const* d_in, const int* in_sizes, int n_in,
                              void* d_out, int out_size) {
    (void)in_sizes; (void)n_in; (void)out_size;
    const float* x  = (const float*)d_in[0];
    const float* W  = (const float*)d_in[1];
    const float* qb = (const float*)d_in[2];
    const float* lw = (const float*)d_in[3];
    const float* lb = (const float*)d_in[4];
    float* out = (float*)d_out;

    cudaFuncSetAttribute(qk_gemm_mma, cudaFuncAttributeMaxDynamicSharedMemorySize, GSMEM);
    cudaFuncSetAttribute(kv_partial_tc, cudaFuncAttributeMaxDynamicSharedMemorySize, KV_SMEM);
    cudaFuncSetAttribute(finalize_tc, cudaFuncAttributeMaxDynamicSharedMemorySize, FIN_SMEM);

    prep_kernel<<<(int)(((size_t)B_ * N_ * C_ / 4) / 256), 256>>>(x, W);
    qk_gemm_mma<<<dim3(CK_ / 128, (B_ * N_) / 128), 256, GSMEM>>>(qb);
    kv_partial_tc<<<dim3(SPLITS, H_, B_), 128, KV_SMEM>>>();
    finalize_tc<<<dim3(16, H_, B_), 256, FIN_SMEM>>>(lw, lb, out);
}